// round 12
// baseline (speedup 1.0000x reference)
#include <cuda_runtime.h>
#include <cuda_bf16.h>
#include <math.h>
#include <stdint.h>

namespace {
constexpr int BROWS  = 4096;
constexpr int UDIM   = 512;
constexpr int THREEU = 1536;
constexpr long long BU = (long long)BROWS * UDIM;
// CTA tile 64x128. Stage: Ah(64r)+Al(64r)+Bh(128r)+Bl(128r), 80B rows
constexpr int STAGE_BYTES = 30720;
constexpr int SMEM_BYTES  = 3 * STAGE_BYTES;   // 92160, 3-stage; 2 CTAs/SM
}

// ------------------------------ PTX helpers --------------------------------
__device__ __forceinline__ uint32_t smem_u32(const void* p) {
    uint32_t a;
    asm("{ .reg .u64 t; cvta.to.shared.u64 t, %1; cvt.u32.u64 %0, t; }" : "=r"(a) : "l"(p));
    return a;
}
__device__ __forceinline__ void cp16(uint32_t s, const void* g) {
    asm volatile("cp.async.cg.shared.global [%0], [%1], 16;" :: "r"(s), "l"(g));
}
#define CP_COMMIT() asm volatile("cp.async.commit_group;" ::: "memory")
#define CP_WAIT1()  asm volatile("cp.async.wait_group 1;" ::: "memory")
#define LDSM4(r0,r1,r2,r3,a) \
    asm volatile("ldmatrix.sync.aligned.m8n8.x4.shared.b16 {%0,%1,%2,%3}, [%4];" \
        : "=r"(r0),"=r"(r1),"=r"(r2),"=r"(r3) : "r"(a))
#define MMA(d,a,b) \
    asm volatile("mma.sync.aligned.m16n8k16.row.col.f32.bf16.bf16.f32 " \
        "{%0,%1,%2,%3},{%4,%5,%6,%7},{%8,%9},{%0,%1,%2,%3};" \
        : "+f"((d)[0]),"+f"((d)[1]),"+f"((d)[2]),"+f"((d)[3]) \
        : "r"((a)[0]),"r"((a)[1]),"r"((a)[2]),"r"((a)[3]),"r"((b)[0]),"r"((b)[1]))

__device__ __forceinline__ uint32_t packhl(float a, float b, bool lo) {
    if (lo) {
        a -= __bfloat162float(__float2bfloat16(a));
        b -= __bfloat162float(__float2bfloat16(b));
    }
    __nv_bfloat162 h2 = __float22bfloat162_rn(make_float2(a, b));
    return *(uint32_t*)&h2;
}

// ------------------------------ scratch ------------------------------------
__device__ __nv_bfloat16 g_inh[2LL*4096*2048], g_inl[2LL*4096*2048];
__device__ __nv_bfloat16 g_cth[4096*512],      g_ctl[4096*512];
__device__ __nv_bfloat16 g_BWh[2*256*2048], g_BWl[2*256*2048];
__device__ __nv_bfloat16 g_BPh[2*256*512],  g_BPl[2*256*512];
__device__ __nv_bfloat16 g_BVh[2*256*256],  g_BVl[2*256*256];
__device__ __nv_bfloat16 g_BDh[512*512],    g_BDl[512*512];
__device__ __nv_bfloat16 g_BCh[512*512],    g_BCl[512*512];
__device__ __nv_bfloat16 g_BKh[2*1536*512], g_BKl[2*1536*512];
__device__ __nv_bfloat16 g_BRh[512*512],    g_BRl[512*512];
__device__ float         g_embf[4096*512];
__device__ __nv_bfloat16 g_embh[4096*512],  g_embl[4096*512];
__device__ float         g_Sf[2*4096*256],  g_Vf[2*4096*256];
__device__ __nv_bfloat16 g_xhh[2*4096*512], g_xhl[2*4096*512];
__device__ float         g_hprev[4096*512];
__device__ __nv_bfloat16 g_croh[4096*512],  g_crol[4096*512];
__device__ float         g_mxi[2LL*4096*1536];
__device__ __nv_bfloat16 g_rhh[4096*512],   g_rhl[4096*512];
__device__ float         g_mh[4096*512];
__device__ float         g_zbias[1536];

// ------------------- batched transpose + bf16 hi/lo split -------------------
struct TDesc {
    const float* src; int sld, Kr, N;
    __nv_bfloat16 *dh, *dl; int dld, ko, Kw;
};
struct TPack { TDesc d[13]; int pre[14]; };

__global__ void tsplit_batch(TPack p)
{
    __shared__ float t[32][33];
    int blk = blockIdx.x;
    int di = 0;
    while (di < 13 && blk >= p.pre[di + 1]) ++di;
    const TDesc& D = p.d[di];
    int local = blk - p.pre[di];
    int nx = D.N >> 5;
    int ty_t = local / nx, tx_t = local % nx;
    int kt = ty_t * 32, nt = tx_t * 32;
    int tx = threadIdx.x, ty = threadIdx.y;    // (32,8)
    #pragma unroll
    for (int i = 0; i < 32; i += 8) {
        int k = kt + ty + i, n = nt + tx;
        t[ty + i][tx] = (k < D.Kr && n < D.N) ? D.src[(size_t)k * D.sld + n] : 0.f;
    }
    __syncthreads();
    #pragma unroll
    for (int i = 0; i < 32; i += 8) {
        int n = nt + ty + i, k = kt + tx;
        if (n < D.N && k < D.Kw) {
            float f = t[tx][ty + i];
            __nv_bfloat16 h = __float2bfloat16(f);
            D.dh[(size_t)n * D.dld + D.ko + k] = h;
            D.dl[(size_t)n * D.dld + D.ko + k] = __float2bfloat16(f - __bfloat162float(h));
        }
    }
}

// ------------------- activation splits --------------------------------------
__global__ void split_inputs(const float* __restrict__ in)
{
    long long i = (long long)blockIdx.x * blockDim.x + threadIdx.x;  // 2*4096*256
    if (i >= 2LL * 4096 * 256) return;
    int c8 = (int)(i & 255);
    long long zr = i >> 8;
    int row = (int)(zr & 4095);
    int z   = (int)(zr >> 12);
    const float* src = in + (size_t)row * 4000 + z * 2000 + c8 * 8;
    long long o = zr * 2048 + c8 * 8;
    #pragma unroll
    for (int e = 0; e < 8; ++e) {
        int c = c8 * 8 + e;
        float f = (c < 2000) ? src[e] : 0.f;
        __nv_bfloat16 h = __float2bfloat16(f);
        g_inh[o + e] = h;
        g_inl[o + e] = __float2bfloat16(f - __bfloat162float(h));
    }
}
__global__ void fsplit(const float* __restrict__ src,
                       __nv_bfloat16* __restrict__ dh, __nv_bfloat16* __restrict__ dl,
                       long long n)
{
    long long i = (long long)blockIdx.x * blockDim.x + threadIdx.x;
    if (i >= n) return;
    float f = src[i];
    __nv_bfloat16 h = __float2bfloat16(f);
    dh[i] = h;
    dl[i] = __float2bfloat16(f - __bfloat162float(h));
}

// ------------------------------ mma.sync GEMM -------------------------------
// C = Ah*Bh + Al*Bh + Ah*Bl, single K-sweep. CTA 64x128, 8 warps (2m x 4n),
// warp tile 32x32, k-chunk 32, 3-stage cp.async (wait_group 1), 2 CTAs/SM.
// EPI: 0 store, 1 +bias, 2 tanh(+bias), 3 add+tanh(+bias)
template <int EPI>
__global__ void __launch_bounds__(256, 2)
mma_gemm(const __nv_bfloat16* Ahi_, const __nv_bfloat16* Alo_, long long lda, long long aZ,
         const __nv_bfloat16* Bhi_, const __nv_bfloat16* Blo_, long long bZ,
         float* C, long long ldc, long long cZ, __nv_bfloat16* Chi, __nv_bfloat16* Clo,
         int K, const float* bias0, const float* bias1,
         const float* add, long long ldadd, int skipZ, int skipXfrom)
{
    const int z = blockIdx.z, tn = blockIdx.x, tm = blockIdx.y;
    if (z == skipZ && tn >= skipXfrom) return;

    extern __shared__ __align__(16) uint8_t smem[];

    const int tid = threadIdx.x, wid = tid >> 5, lane = tid & 31;
    const int m0 = tm * 64, n0 = tn * 128;
    const int wm = wid & 1, wn = wid >> 1;       // 2m x 4n, warp tile 32x32

    const __nv_bfloat16* Ahi = Ahi_ + z * aZ;
    const __nv_bfloat16* Alo = Alo_ + z * aZ;
    const __nv_bfloat16* Bhi = Bhi_ + z * bZ;
    const __nv_bfloat16* Blo = Blo_ + z * bZ;
    if (C)   C   += z * cZ;
    if (Chi) { Chi += z * cZ; Clo += z * cZ; }
    const float* biasp = (z == 0) ? bias0 : bias1;

    const uint32_t sbase = smem_u32(smem);
    // per stage: Ah +0 (64r), Al +5120 (64r), Bh +10240 (128r), Bl +20480 (128r)
    uint32_t sS_[3], aB_[3], bB_[3];
    #pragma unroll
    for (int s = 0; s < 3; ++s) {
        sS_[s] = sbase + s * STAGE_BYTES;
        aB_[s] = sS_[s] + (wm * 32 + (lane & 15)) * 80 + (lane >> 4) * 16;
        bB_[s] = sS_[s] + 10240
               + (wn * 32 + (lane & 7) + ((lane >> 4) & 1) * 8) * 80
               + ((lane >> 3) & 1) * 16;
    }
    const int ldr = tid >> 2, ldseg = tid & 3;   // 64 rows, 4 segs of 16B

    float acc[2][4][4];
    #pragma unroll
    for (int a = 0; a < 2; ++a)
        #pragma unroll
        for (int b = 0; b < 4; ++b)
            #pragma unroll
            for (int c = 0; c < 4; ++c) acc[a][b][c] = 0.f;

    const int nch = K / 32;

    auto issue = [&](int cc) {
        if (cc < nch) {
            const int ko = cc * 32, st = cc % 3;
            const uint32_t sg = sS_[st];
            const uint32_t so = ldr * 80 + ldseg * 16;
            const size_t ao = (size_t)(m0 + ldr) * lda + ko + ldseg * 8;
            cp16(sg +        so, Ahi + ao);
            cp16(sg + 5120 + so, Alo + ao);
            #pragma unroll
            for (int it = 0; it < 2; ++it) {
                int r = ldr + it * 64;
                uint32_t so2 = r * 80 + ldseg * 16;
                const size_t bo = (size_t)(n0 + r) * K + ko + ldseg * 8;
                cp16(sg + 10240 + so2, Bhi + bo);
                cp16(sg + 20480 + so2, Blo + bo);
            }
        }
        CP_COMMIT();
    };

    issue(0);
    issue(1);
    for (int cc = 0; cc < nch; ++cc) {
        const int st = cc % 3;
        CP_WAIT1();
        __syncthreads();
        issue(cc + 2);
        const uint32_t aB = aB_[st], bB = bB_[st];
        #pragma unroll
        for (int s = 0; s < 2; ++s) {
            uint32_t bh[4][2], bl[4][2];
            #pragma unroll
            for (int np = 0; np < 2; ++np) {
                LDSM4(bh[2*np][0], bh[2*np][1], bh[2*np+1][0], bh[2*np+1][1],
                      bB + np * 16 * 80 + s * 32);
                LDSM4(bl[2*np][0], bl[2*np][1], bl[2*np+1][0], bl[2*np+1][1],
                      bB + 10240 + np * 16 * 80 + s * 32);
            }
            #pragma unroll
            for (int mt = 0; mt < 2; ++mt) {
                uint32_t ah[4], al[4];
                LDSM4(ah[0], ah[1], ah[2], ah[3], aB + mt * 16 * 80 + s * 32);
                LDSM4(al[0], al[1], al[2], al[3], aB + 5120 + mt * 16 * 80 + s * 32);
                #pragma unroll
                for (int nt = 0; nt < 4; ++nt) {
                    MMA(acc[mt][nt], ah, bh[nt]);
                    MMA(acc[mt][nt], al, bh[nt]);
                    MMA(acc[mt][nt], ah, bl[nt]);
                }
            }
        }
    }

    // ------------------------------ epilogue --------------------------------
    const int tig = lane & 3, gid = lane >> 2;
    #pragma unroll
    for (int mt = 0; mt < 2; ++mt) {
        #pragma unroll
        for (int half = 0; half < 2; ++half) {
            const int row = m0 + wm * 32 + mt * 16 + gid + half * 8;
            #pragma unroll
            for (int nt = 0; nt < 4; ++nt) {
                const int col = n0 + wn * 32 + nt * 8 + 2 * tig;
                float x0 = acc[mt][nt][half * 2 + 0];
                float x1 = acc[mt][nt][half * 2 + 1];
                if (EPI == 1)      { x0 += biasp[col]; x1 += biasp[col + 1]; }
                else if (EPI == 2) { x0 = tanhf(x0 + biasp[col]); x1 = tanhf(x1 + biasp[col + 1]); }
                else if (EPI == 3) {
                    x0 = add[(size_t)row * ldadd + col]     + tanhf(x0 + biasp[col]);
                    x1 = add[(size_t)row * ldadd + col + 1] + tanhf(x1 + biasp[col + 1]);
                }
                if (C) *(float2*)(C + (size_t)row * ldc + col) = make_float2(x0, x1);
                if (Chi) {
                    *(uint32_t*)(Chi + (size_t)row * ldc + col) = packhl(x0, x1, false);
                    *(uint32_t*)(Clo + (size_t)row * ldc + col) = packhl(x0, x1, true);
                }
            }
        }
    }
}

// ------------------------------ attention + crohis_new ----------------------
__global__ void __launch_bounds__(256)
attn_kernel(const float* __restrict__ crohis_tm, float* __restrict__ out_crohis)
{
    __shared__ float red[256];
    const int row = blockIdx.x, c = threadIdx.x;
    const float* emb = g_embf + (long long)row * 512;
    #pragma unroll
    for (int side = 0; side < 2; side++) {
        const float* S = g_Sf + (long long)side * (BROWS*256) + (long long)row * 256;
        const float* V = g_Vf + (long long)side * (BROWS*256) + (long long)row * 256;
        float l = tanhf(S[c]) * V[c];
        red[c] = l; __syncthreads();
        #pragma unroll
        for (int s = 128; s > 0; s >>= 1) { if (c < s) red[c] = fmaxf(red[c], red[c+s]); __syncthreads(); }
        float m = red[0]; __syncthreads();
        float e = __expf(l - m);
        red[c] = e; __syncthreads();
        #pragma unroll
        for (int s = 128; s > 0; s >>= 1) { if (c < s) red[c] += red[c+s]; __syncthreads(); }
        float ssum = red[0]; __syncthreads();
        int col = side * 256 + c;
        float xv = emb[col] * (e / ssum);
        long long gi = (long long)row * 512 + col;
        __nv_bfloat16 h = __float2bfloat16(xv);
        g_xhh[gi] = h;
        g_xhl[gi] = __float2bfloat16(xv - __bfloat162float(h));
        out_crohis[gi] = 0.5f * crohis_tm[gi] + 0.5f * xv;
    }
}

__global__ void rgate_kernel()
{
    int idx = blockIdx.x * blockDim.x + threadIdx.x;
    if (idx >= BROWS * UDIM) return;
    int row = idx >> 9, col = idx & 511;
    const float* mx = g_mxi + (long long)row * THREEU;
    const float* mi = g_mxi + (long long)BROWS * THREEU + (long long)row * THREEU;
    float r = 1.0f / (1.0f + __expf(-(mx[col + 512] + mi[col + 512])));
    float rh = r * g_hprev[idx];
    __nv_bfloat16 h = __float2bfloat16(rh);
    g_rhh[idx] = h;
    g_rhl[idx] = __float2bfloat16(rh - __bfloat162float(h));
}

__global__ void gru_kernel(float* __restrict__ h_out)
{
    int idx = blockIdx.x * blockDim.x + threadIdx.x;
    if (idx >= BROWS * UDIM) return;
    int row = idx >> 9, col = idx & 511;
    const float* mx = g_mxi + (long long)row * THREEU;
    const float* mi = g_mxi + (long long)BROWS * THREEU + (long long)row * THREEU;
    float z  = 1.0f / (1.0f + __expf(-(mx[col] + mi[col])));
    float hp = g_hprev[idx];
    float hh = tanhf(mx[col + 1024] + g_mh[idx]);
    h_out[idx] = z * hp + (1.0f - z) * hh;
}

// ------------------------------ launch --------------------------------------
extern "C" void kernel_launch(void* const* d_in, const int* in_sizes, int n_in,
                              void* d_out, int out_size)
{
    const float* inputs    = (const float*)d_in[0];
    const float* h_tm1     = (const float*)d_in[1];
    const float* crohis_tm = (const float*)d_in[2];
    const float* W1   = (const float*)d_in[3];
    const float* W2   = (const float*)d_in[4];
    const float* w12  = (const float*)d_in[5];
    const float* u12  = (const float*)d_in[6];
    const float* v12  = (const float*)d_in[7];
    const float* w21  = (const float*)d_in[8];
    const float* u21  = (const float*)d_in[9];
    const float* v21  = (const float*)d_in[10];
    const float* croW = (const float*)d_in[11];
    const float* croB = (const float*)d_in[12];
    const float* decompW = (const float*)d_in[13];
    const float* decompB = (const float*)d_in[14];
    const float* kern  = (const float*)d_in[15];
    const float* rkern = (const float*)d_in[16];
    const float* bias  = (const float*)d_in[17];
    float* out = (float*)d_out;

    static bool attr_done = false;
    if (!attr_done) {
        cudaFuncSetAttribute(mma_gemm<0>, cudaFuncAttributeMaxDynamicSharedMemorySize, SMEM_BYTES);
        cudaFuncSetAttribute(mma_gemm<1>, cudaFuncAttributeMaxDynamicSharedMemorySize, SMEM_BYTES);
        cudaFuncSetAttribute(mma_gemm<2>, cudaFuncAttributeMaxDynamicSharedMemorySize, SMEM_BYTES);
        cudaFuncSetAttribute(mma_gemm<3>, cudaFuncAttributeMaxDynamicSharedMemorySize, SMEM_BYTES);
        cudaFuncSetAttribute(mma_gemm<0>, cudaFuncAttributePreferredSharedMemoryCarveout, 100);
        cudaFuncSetAttribute(mma_gemm<1>, cudaFuncAttributePreferredSharedMemoryCarveout, 100);
        cudaFuncSetAttribute(mma_gemm<2>, cudaFuncAttributePreferredSharedMemoryCarveout, 100);
        cudaFuncSetAttribute(mma_gemm<3>, cudaFuncAttributePreferredSharedMemoryCarveout, 100);
        attr_done = true;
    }

    __nv_bfloat16 *pINh,*pINl,*pCTh,*pCTl,*pBWh,*pBWl,*pBPh,*pBPl,*pBVh,*pBVl,
                  *pBDh,*pBDl,*pBCh,*pBCl,*pBKh,*pBKl,*pBRh,*pBRl,
                  *pEh,*pEl,*pXHh,*pXHl,*pCRh,*pCRl,*pRHh,*pRHl;
    float *pEf,*pSf,*pVf,*pHP,*pMXI,*pMH,*pZB;
    cudaGetSymbolAddress((void**)&pINh,g_inh); cudaGetSymbolAddress((void**)&pINl,g_inl);
    cudaGetSymbolAddress((void**)&pCTh,g_cth); cudaGetSymbolAddress((void**)&pCTl,g_ctl);
    cudaGetSymbolAddress((void**)&pBWh,g_BWh); cudaGetSymbolAddress((void**)&pBWl,g_BWl);
    cudaGetSymbolAddress((void**)&pBPh,g_BPh); cudaGetSymbolAddress((void**)&pBPl,g_BPl);
    cudaGetSymbolAddress((void**)&pBVh,g_BVh); cudaGetSymbolAddress((void**)&pBVl,g_BVl);
    cudaGetSymbolAddress((void**)&pBDh,g_BDh); cudaGetSymbolAddress((void**)&pBDl,g_BDl);
    cudaGetSymbolAddress((void**)&pBCh,g_BCh); cudaGetSymbolAddress((void**)&pBCl,g_BCl);
    cudaGetSymbolAddress((void**)&pBKh,g_BKh); cudaGetSymbolAddress((void**)&pBKl,g_BKl);
    cudaGetSymbolAddress((void**)&pBRh,g_BRh); cudaGetSymbolAddress((void**)&pBRl,g_BRl);
    cudaGetSymbolAddress((void**)&pEf,g_embf);
    cudaGetSymbolAddress((void**)&pEh,g_embh); cudaGetSymbolAddress((void**)&pEl,g_embl);
    cudaGetSymbolAddress((void**)&pSf,g_Sf);   cudaGetSymbolAddress((void**)&pVf,g_Vf);
    cudaGetSymbolAddress((void**)&pXHh,g_xhh); cudaGetSymbolAddress((void**)&pXHl,g_xhl);
    cudaGetSymbolAddress((void**)&pHP,g_hprev);
    cudaGetSymbolAddress((void**)&pCRh,g_croh); cudaGetSymbolAddress((void**)&pCRl,g_crol);
    cudaGetSymbolAddress((void**)&pMXI,g_mxi);
    cudaGetSymbolAddress((void**)&pRHh,g_rhh); cudaGetSymbolAddress((void**)&pRHl,g_rhl);
    cudaGetSymbolAddress((void**)&pMH,g_mh);   cudaGetSymbolAddress((void**)&pZB,g_zbias);

    // batched weight transpose+split (one launch)
    TPack tp;
    TDesc* d = tp.d;
    d[0]  = {W1,      256, 2000, 256,  pBWh,           pBWl,           2048, 0,   2048};
    d[1]  = {W2,      256, 2000, 256,  pBWh+256*2048,  pBWl+256*2048,  2048, 0,   2048};
    d[2]  = {w12,     256, 256,  256,  pBPh,           pBPl,           512,  0,   256};
    d[3]  = {u12,     256, 256,  256,  pBPh,           pBPl,           512,  256, 256};
    d[4]  = {u21,     256, 256,  256,  pBPh+256*512,   pBPl+256*512,   512,  0,   256};
    d[5]  = {w21,     256, 256,  256,  pBPh+256*512,   pBPl+256*512,   512,  256, 256};
    d[6]  = {v12,     256, 256,  256,  pBVh,           pBVl,           256,  0,   256};
    d[7]  = {v21,     256, 256,  256,  pBVh+256*256,   pBVl+256*256,   256,  0,   256};
    d[8]  = {decompW, 512, 512,  512,  pBDh,           pBDl,           512,  0,   512};
    d[9]  = {croW,    512, 512,  512,  pBCh,           pBCl,           512,  0,   512};
    d[10] = {kern,    1536, 512, 1536, pBKh,           pBKl,           512,  0,   512};
    d[11] = {rkern,   1536, 512, 1536, pBKh+1536*512,  pBKl+1536*512,  512,  0,   512};
    d[12] = {rkern+1024, 1536, 512, 512, pBRh,         pBRl,           512,  0,   512};
    tp.pre[0] = 0;
    for (int i = 0; i < 13; ++i)
        tp.pre[i+1] = tp.pre[i] + (d[i].N >> 5) * (d[i].Kw >> 5);
    tsplit_batch<<<tp.pre[13], dim3(32, 8)>>>(tp);

    split_inputs<<<(2*4096*256 + 255)/256, 256>>>(inputs);
    fsplit<<<(int)((BU + 255)/256), 256>>>(crohis_tm, pCTh, pCTl, BU);

    // emb = inputs @ W  (z-batched, K padded to 2048)  grid 256
    mma_gemm<0><<<dim3(2,64,2), 256, SMEM_BYTES>>>(
        pINh, pINl, 2048, 4096LL*2048, pBWh, pBWl, (long long)256*2048,
        pEf, 512, 256, pEh, pEl, 2048, nullptr, nullptr, nullptr, 0, -1, 0);
    // S = emb @ [w;u]   (K=512)  grid 256
    mma_gemm<0><<<dim3(2,64,2), 256, SMEM_BYTES>>>(
        pEh, pEl, 512, 0, pBPh, pBPl, (long long)256*512,
        pSf, 256, (long long)BROWS*256, nullptr, nullptr, 512,
        nullptr, nullptr, nullptr, 0, -1, 0);
    // V12 = emb2 @ v12, V21 = emb1 @ v21  (K=256)  grid 256
    mma_gemm<0><<<dim3(2,64,2), 256, SMEM_BYTES>>>(
        pEh+256, pEl+256, 512, -256, pBVh, pBVl, (long long)256*256,
        pVf, 256, (long long)BROWS*256, nullptr, nullptr, 256,
        nullptr, nullptr, nullptr, 0, -1, 0);
    // attention + crohis_new (second half of d_out)
    attn_kernel<<<BROWS, 256>>>(crohis_tm, out + BU);
    // cro = tanh(crohis_tm @ decompW + decompB)  grid 256
    mma_gemm<2><<<dim3(4,64,1), 256, SMEM_BYTES>>>(
        pCTh, pCTl, 512, 0, pBDh, pBDl, 0,
        nullptr, 512, 0, pCRh, pCRl, 512, decompB, decompB, nullptr, 0, -1, 0);
    // h_prev = h_tm1 + tanh(cro @ croW + croB)  grid 256
    mma_gemm<3><<<dim3(4,64,1), 256, SMEM_BYTES>>>(
        pCRh, pCRl, 512, 0, pBCh, pBCl, 0,
        pHP, 512, 0, pXHh + BU, pXHl + BU, 512, croB, croB, h_tm1, 512, -1, 0);
    // mx = x @ kernel + bias ; mi(first 1024 cols) = h_prev @ rkern  grid 1280
    mma_gemm<1><<<dim3(12,64,2), 256, SMEM_BYTES>>>(
        pXHh, pXHl, 512, BU, pBKh, pBKl, (long long)1536*512,
        pMXI, 1536, (long long)BROWS*1536, nullptr, nullptr, 512,
        bias, pZB, nullptr, 0, 1, 8);
    // r gate, rh = r*h_prev (hi/lo)
    rgate_kernel<<<(BROWS*UDIM + 255)/256, 256>>>();
    // mh = rh @ rkern[:, 2U:]  grid 256
    mma_gemm<0><<<dim3(4,64,1), 256, SMEM_BYTES>>>(
        pRHh, pRHl, 512, 0, pBRh, pBRl, 0,
        pMH, 512, 0, nullptr, nullptr, 512, nullptr, nullptr, nullptr, 0, -1, 0);
    // GRU combine -> h (first half of d_out)
    gru_kernel<<<(BROWS*UDIM + 255)/256, 256>>>(out);
}

// round 13
// speedup vs baseline: 1.2389x; 1.2389x over previous
#include <cuda_runtime.h>
#include <cuda_fp16.h>
#include <math.h>
#include <stdint.h>

namespace {
constexpr int BROWS  = 4096;
constexpr int UDIM   = 512;
constexpr int THREEU = 1536;
constexpr long long BU = (long long)BROWS * UDIM;
// CTA tile 64x128. Stage: Ah(64r)+Al(64r)+Bh(128r), 80B rows
constexpr int STAGE_BYTES = 20480;
constexpr int SMEM_BYTES  = 2 * STAGE_BYTES;   // 40960 -> 2 CTAs/SM easily
}

// ------------------------------ PTX helpers --------------------------------
__device__ __forceinline__ uint32_t smem_u32(const void* p) {
    uint32_t a;
    asm("{ .reg .u64 t; cvta.to.shared.u64 t, %1; cvt.u32.u64 %0, t; }" : "=r"(a) : "l"(p));
    return a;
}
__device__ __forceinline__ void cp16(uint32_t s, const void* g) {
    asm volatile("cp.async.cg.shared.global [%0], [%1], 16;" :: "r"(s), "l"(g));
}
#define CP_COMMIT() asm volatile("cp.async.commit_group;" ::: "memory")
#define CP_WAIT0()  asm volatile("cp.async.wait_group 0;" ::: "memory")
#define LDSM4(r0,r1,r2,r3,a) \
    asm volatile("ldmatrix.sync.aligned.m8n8.x4.shared.b16 {%0,%1,%2,%3}, [%4];" \
        : "=r"(r0),"=r"(r1),"=r"(r2),"=r"(r3) : "r"(a))
#define MMA(d,a,b) \
    asm volatile("mma.sync.aligned.m16n8k16.row.col.f32.f16.f16.f32 " \
        "{%0,%1,%2,%3},{%4,%5,%6,%7},{%8,%9},{%0,%1,%2,%3};" \
        : "+f"((d)[0]),"+f"((d)[1]),"+f"((d)[2]),"+f"((d)[3]) \
        : "r"((a)[0]),"r"((a)[1]),"r"((a)[2]),"r"((a)[3]),"r"((b)[0]),"r"((b)[1]))

__device__ __forceinline__ uint32_t packhl(float a, float b, bool lo) {
    if (lo) {
        a -= __half2float(__float2half_rn(a));
        b -= __half2float(__float2half_rn(b));
    }
    __half2 h2 = __floats2half2_rn(a, b);
    return *(uint32_t*)&h2;
}

// ------------------------------ scratch ------------------------------------
__device__ __half g_inh[2LL*4096*2048], g_inl[2LL*4096*2048];
__device__ __half g_cth[4096*512],      g_ctl[4096*512];
__device__ __half g_BW[2*256*2048];
__device__ __half g_BP[2*256*512];
__device__ __half g_BV[2*256*256];
__device__ __half g_BD[512*512];
__device__ __half g_BC[512*512];
__device__ __half g_BK[2*1536*512];
__device__ __half g_BR[512*512];
__device__ float  g_embf[4096*512];
__device__ __half g_embh[4096*512],  g_embl[4096*512];
__device__ float  g_Sf[2*4096*256],  g_Vf[2*4096*256];
__device__ __half g_xhh[2*4096*512], g_xhl[2*4096*512];
__device__ float  g_hprev[4096*512];
__device__ __half g_croh[4096*512],  g_crol[4096*512];
__device__ float  g_mxi[2LL*4096*1536];
__device__ __half g_rhh[4096*512],   g_rhl[4096*512];
__device__ float  g_mh[4096*512];
__device__ float  g_zbias[1536];

// ------------------- batched transpose + fp16 convert (weights) -------------
struct TDesc {
    const float* src; int sld, Kr, N;
    __half* dh; int dld, ko, Kw;
};
struct TPack { TDesc d[13]; int pre[14]; };

__global__ void tsplit_batch(TPack p)
{
    __shared__ float t[32][33];
    int blk = blockIdx.x;
    int di = 0;
    while (di < 13 && blk >= p.pre[di + 1]) ++di;
    const TDesc& D = p.d[di];
    int local = blk - p.pre[di];
    int nx = D.N >> 5;
    int ty_t = local / nx, tx_t = local % nx;
    int kt = ty_t * 32, nt = tx_t * 32;
    int tx = threadIdx.x, ty = threadIdx.y;    // (32,8)
    #pragma unroll
    for (int i = 0; i < 32; i += 8) {
        int k = kt + ty + i, n = nt + tx;
        t[ty + i][tx] = (k < D.Kr && n < D.N) ? D.src[(size_t)k * D.sld + n] : 0.f;
    }
    __syncthreads();
    #pragma unroll
    for (int i = 0; i < 32; i += 8) {
        int n = nt + ty + i, k = kt + tx;
        if (n < D.N && k < D.Kw)
            D.dh[(size_t)n * D.dld + D.ko + k] = __float2half_rn(t[tx][ty + i]);
    }
}

// ------------------- activation splits (fp16 hi/lo) --------------------------
__global__ void split_inputs(const float* __restrict__ in)
{
    long long i = (long long)blockIdx.x * blockDim.x + threadIdx.x;  // 2*4096*256
    if (i >= 2LL * 4096 * 256) return;
    int c8 = (int)(i & 255);
    long long zr = i >> 8;
    int row = (int)(zr & 4095);
    int z   = (int)(zr >> 12);
    const float* src = in + (size_t)row * 4000 + z * 2000 + c8 * 8;
    long long o = zr * 2048 + c8 * 8;
    #pragma unroll
    for (int e = 0; e < 8; ++e) {
        int c = c8 * 8 + e;
        float f = (c < 2000) ? src[e] : 0.f;
        __half h = __float2half_rn(f);
        g_inh[o + e] = h;
        g_inl[o + e] = __float2half_rn(f - __half2float(h));
    }
}
__global__ void fsplit(const float* __restrict__ src,
                       __half* __restrict__ dh, __half* __restrict__ dl,
                       long long n)
{
    long long i = (long long)blockIdx.x * blockDim.x + threadIdx.x;
    if (i >= n) return;
    float f = src[i];
    __half h = __float2half_rn(f);
    dh[i] = h;
    dl[i] = __float2half_rn(f - __half2float(h));
}

// ------------------------------ mma.sync GEMM -------------------------------
// C = (Ah+Al) @ Bh^T  (A fp16 hi/lo split, B single fp16; 2 MMAs per tile).
// CTA 64x128, 8 warps (2m x 4n), warp tile 32x32, k-chunk 32, 2-stage, 2 CTAs/SM.
// EPI: 0 store, 1 +bias, 2 tanh(+bias), 3 add+tanh(+bias)
template <int EPI>
__global__ void __launch_bounds__(256, 2)
mma_gemm(const __half* Ahi_, const __half* Alo_, long long lda, long long aZ,
         const __half* Bhi_, long long bZ,
         float* C, long long ldc, long long cZ, __half* Chi, __half* Clo,
         int K, const float* bias0, const float* bias1,
         const float* add, long long ldadd, int skipZ, int skipXfrom)
{
    const int z = blockIdx.z, tn = blockIdx.x, tm = blockIdx.y;
    if (z == skipZ && tn >= skipXfrom) return;

    extern __shared__ __align__(16) uint8_t smem[];

    const int tid = threadIdx.x, wid = tid >> 5, lane = tid & 31;
    const int m0 = tm * 64, n0 = tn * 128;
    const int wm = wid & 1, wn = wid >> 1;       // 2m x 4n, warp tile 32x32

    const __half* Ahi = Ahi_ + z * aZ;
    const __half* Alo = Alo_ + z * aZ;
    const __half* Bhi = Bhi_ + z * bZ;
    if (C)   C   += z * cZ;
    if (Chi) { Chi += z * cZ; Clo += z * cZ; }
    const float* biasp = (z == 0) ? bias0 : bias1;

    const uint32_t sbase = smem_u32(smem);
    // per stage: Ah +0 (64r), Al +5120 (64r), Bh +10240 (128r) ; rows 80B
    uint32_t sS_[2], aB_[2], bB_[2];
    #pragma unroll
    for (int s = 0; s < 2; ++s) {
        sS_[s] = sbase + s * STAGE_BYTES;
        aB_[s] = sS_[s] + (wm * 32 + (lane & 15)) * 80 + (lane >> 4) * 16;
        bB_[s] = sS_[s] + 10240
               + (wn * 32 + (lane & 7) + ((lane >> 4) & 1) * 8) * 80
               + ((lane >> 3) & 1) * 16;
    }
    const int ldr = tid >> 2, ldseg = tid & 3;   // 64 rows, 4 segs of 16B

    float acc[2][4][4];
    #pragma unroll
    for (int a = 0; a < 2; ++a)
        #pragma unroll
        for (int b = 0; b < 4; ++b)
            #pragma unroll
            for (int c = 0; c < 4; ++c) acc[a][b][c] = 0.f;

    const int nch = K / 32;

    auto issue = [&](int cc) {
        const int ko = cc * 32, st = cc & 1;
        const uint32_t sg = sS_[st];
        const uint32_t so = ldr * 80 + ldseg * 16;
        const size_t ao = (size_t)(m0 + ldr) * lda + ko + ldseg * 8;
        cp16(sg +        so, Ahi + ao);
        cp16(sg + 5120 + so, Alo + ao);
        #pragma unroll
        for (int it = 0; it < 2; ++it) {
            int r = ldr + it * 64;
            uint32_t so2 = r * 80 + ldseg * 16;
            cp16(sg + 10240 + so2, Bhi + (size_t)(n0 + r) * K + ko + ldseg * 8);
        }
        CP_COMMIT();
    };

    issue(0);
    for (int cc = 0; cc < nch; ++cc) {
        const int st = cc & 1;
        CP_WAIT0();
        __syncthreads();
        if (cc + 1 < nch) issue(cc + 1);
        const uint32_t aB = aB_[st], bB = bB_[st];
        #pragma unroll
        for (int s = 0; s < 2; ++s) {
            uint32_t bh[4][2];
            #pragma unroll
            for (int np = 0; np < 2; ++np)
                LDSM4(bh[2*np][0], bh[2*np][1], bh[2*np+1][0], bh[2*np+1][1],
                      bB + np * 16 * 80 + s * 32);
            #pragma unroll
            for (int mt = 0; mt < 2; ++mt) {
                uint32_t ah[4], al[4];
                LDSM4(ah[0], ah[1], ah[2], ah[3], aB + mt * 16 * 80 + s * 32);
                LDSM4(al[0], al[1], al[2], al[3], aB + 5120 + mt * 16 * 80 + s * 32);
                #pragma unroll
                for (int nt = 0; nt < 4; ++nt) {
                    MMA(acc[mt][nt], ah, bh[nt]);
                    MMA(acc[mt][nt], al, bh[nt]);
                }
            }
        }
        __syncthreads();
    }

    // ------------------------------ epilogue --------------------------------
    const int tig = lane & 3, gid = lane >> 2;
    #pragma unroll
    for (int mt = 0; mt < 2; ++mt) {
        #pragma unroll
        for (int half = 0; half < 2; ++half) {
            const int row = m0 + wm * 32 + mt * 16 + gid + half * 8;
            #pragma unroll
            for (int nt = 0; nt < 4; ++nt) {
                const int col = n0 + wn * 32 + nt * 8 + 2 * tig;
                float x0 = acc[mt][nt][half * 2 + 0];
                float x1 = acc[mt][nt][half * 2 + 1];
                if (EPI == 1)      { x0 += biasp[col]; x1 += biasp[col + 1]; }
                else if (EPI == 2) { x0 = tanhf(x0 + biasp[col]); x1 = tanhf(x1 + biasp[col + 1]); }
                else if (EPI == 3) {
                    x0 = add[(size_t)row * ldadd + col]     + tanhf(x0 + biasp[col]);
                    x1 = add[(size_t)row * ldadd + col + 1] + tanhf(x1 + biasp[col + 1]);
                }
                if (C) *(float2*)(C + (size_t)row * ldc + col) = make_float2(x0, x1);
                if (Chi) {
                    *(uint32_t*)(Chi + (size_t)row * ldc + col) = packhl(x0, x1, false);
                    *(uint32_t*)(Clo + (size_t)row * ldc + col) = packhl(x0, x1, true);
                }
            }
        }
    }
}

// ------------------------------ attention + crohis_new ----------------------
__global__ void __launch_bounds__(256)
attn_kernel(const float* __restrict__ crohis_tm, float* __restrict__ out_crohis)
{
    __shared__ float red[256];
    const int row = blockIdx.x, c = threadIdx.x;
    const float* emb = g_embf + (long long)row * 512;
    #pragma unroll
    for (int side = 0; side < 2; side++) {
        const float* S = g_Sf + (long long)side * (BROWS*256) + (long long)row * 256;
        const float* V = g_Vf + (long long)side * (BROWS*256) + (long long)row * 256;
        float l = tanhf(S[c]) * V[c];
        red[c] = l; __syncthreads();
        #pragma unroll
        for (int s = 128; s > 0; s >>= 1) { if (c < s) red[c] = fmaxf(red[c], red[c+s]); __syncthreads(); }
        float m = red[0]; __syncthreads();
        float e = __expf(l - m);
        red[c] = e; __syncthreads();
        #pragma unroll
        for (int s = 128; s > 0; s >>= 1) { if (c < s) red[c] += red[c+s]; __syncthreads(); }
        float ssum = red[0]; __syncthreads();
        int col = side * 256 + c;
        float xv = emb[col] * (e / ssum);
        long long gi = (long long)row * 512 + col;
        __half h = __float2half_rn(xv);
        g_xhh[gi] = h;
        g_xhl[gi] = __float2half_rn(xv - __half2float(h));
        out_crohis[gi] = 0.5f * crohis_tm[gi] + 0.5f * xv;
    }
}

__global__ void rgate_kernel()
{
    int idx = blockIdx.x * blockDim.x + threadIdx.x;
    if (idx >= BROWS * UDIM) return;
    int row = idx >> 9, col = idx & 511;
    const float* mx = g_mxi + (long long)row * THREEU;
    const float* mi = g_mxi + (long long)BROWS * THREEU + (long long)row * THREEU;
    float r = 1.0f / (1.0f + __expf(-(mx[col + 512] + mi[col + 512])));
    float rh = r * g_hprev[idx];
    __half h = __float2half_rn(rh);
    g_rhh[idx] = h;
    g_rhl[idx] = __float2half_rn(rh - __half2float(h));
}

__global__ void gru_kernel(float* __restrict__ h_out)
{
    int idx = blockIdx.x * blockDim.x + threadIdx.x;
    if (idx >= BROWS * UDIM) return;
    int row = idx >> 9, col = idx & 511;
    const float* mx = g_mxi + (long long)row * THREEU;
    const float* mi = g_mxi + (long long)BROWS * THREEU + (long long)row * THREEU;
    float z  = 1.0f / (1.0f + __expf(-(mx[col] + mi[col])));
    float hp = g_hprev[idx];
    float hh = tanhf(mx[col + 1024] + g_mh[idx]);
    h_out[idx] = z * hp + (1.0f - z) * hh;
}

// ------------------------------ launch --------------------------------------
extern "C" void kernel_launch(void* const* d_in, const int* in_sizes, int n_in,
                              void* d_out, int out_size)
{
    const float* inputs    = (const float*)d_in[0];
    const float* h_tm1     = (const float*)d_in[1];
    const float* crohis_tm = (const float*)d_in[2];
    const float* W1   = (const float*)d_in[3];
    const float* W2   = (const float*)d_in[4];
    const float* w12  = (const float*)d_in[5];
    const float* u12  = (const float*)d_in[6];
    const float* v12  = (const float*)d_in[7];
    const float* w21  = (const float*)d_in[8];
    const float* u21  = (const float*)d_in[9];
    const float* v21  = (const float*)d_in[10];
    const float* croW = (const float*)d_in[11];
    const float* croB = (const float*)d_in[12];
    const float* decompW = (const float*)d_in[13];
    const float* decompB = (const float*)d_in[14];
    const float* kern  = (const float*)d_in[15];
    const float* rkern = (const float*)d_in[16];
    const float* bias  = (const float*)d_in[17];
    float* out = (float*)d_out;

    static bool attr_done = false;
    if (!attr_done) {
        cudaFuncSetAttribute(mma_gemm<0>, cudaFuncAttributeMaxDynamicSharedMemorySize, SMEM_BYTES);
        cudaFuncSetAttribute(mma_gemm<1>, cudaFuncAttributeMaxDynamicSharedMemorySize, SMEM_BYTES);
        cudaFuncSetAttribute(mma_gemm<2>, cudaFuncAttributeMaxDynamicSharedMemorySize, SMEM_BYTES);
        cudaFuncSetAttribute(mma_gemm<3>, cudaFuncAttributeMaxDynamicSharedMemorySize, SMEM_BYTES);
        cudaFuncSetAttribute(mma_gemm<0>, cudaFuncAttributePreferredSharedMemoryCarveout, 100);
        cudaFuncSetAttribute(mma_gemm<1>, cudaFuncAttributePreferredSharedMemoryCarveout, 100);
        cudaFuncSetAttribute(mma_gemm<2>, cudaFuncAttributePreferredSharedMemoryCarveout, 100);
        cudaFuncSetAttribute(mma_gemm<3>, cudaFuncAttributePreferredSharedMemoryCarveout, 100);
        attr_done = true;
    }

    __half *pINh,*pINl,*pCTh,*pCTl,*pBW,*pBP,*pBV,*pBD,*pBC,*pBK,*pBR,
           *pEh,*pEl,*pXHh,*pXHl,*pCRh,*pCRl,*pRHh,*pRHl;
    float *pEf,*pSf,*pVf,*pHP,*pMXI,*pMH,*pZB;
    cudaGetSymbolAddress((void**)&pINh,g_inh); cudaGetSymbolAddress((void**)&pINl,g_inl);
    cudaGetSymbolAddress((void**)&pCTh,g_cth); cudaGetSymbolAddress((void**)&pCTl,g_ctl);
    cudaGetSymbolAddress((void**)&pBW,g_BW);
    cudaGetSymbolAddress((void**)&pBP,g_BP);
    cudaGetSymbolAddress((void**)&pBV,g_BV);
    cudaGetSymbolAddress((void**)&pBD,g_BD);
    cudaGetSymbolAddress((void**)&pBC,g_BC);
    cudaGetSymbolAddress((void**)&pBK,g_BK);
    cudaGetSymbolAddress((void**)&pBR,g_BR);
    cudaGetSymbolAddress((void**)&pEf,g_embf);
    cudaGetSymbolAddress((void**)&pEh,g_embh); cudaGetSymbolAddress((void**)&pEl,g_embl);
    cudaGetSymbolAddress((void**)&pSf,g_Sf);   cudaGetSymbolAddress((void**)&pVf,g_Vf);
    cudaGetSymbolAddress((void**)&pXHh,g_xhh); cudaGetSymbolAddress((void**)&pXHl,g_xhl);
    cudaGetSymbolAddress((void**)&pHP,g_hprev);
    cudaGetSymbolAddress((void**)&pCRh,g_croh); cudaGetSymbolAddress((void**)&pCRl,g_crol);
    cudaGetSymbolAddress((void**)&pMXI,g_mxi);
    cudaGetSymbolAddress((void**)&pRHh,g_rhh); cudaGetSymbolAddress((void**)&pRHl,g_rhl);
    cudaGetSymbolAddress((void**)&pMH,g_mh);   cudaGetSymbolAddress((void**)&pZB,g_zbias);

    // batched weight transpose+convert (one launch)
    TPack tp;
    TDesc* d = tp.d;
    d[0]  = {W1,      256, 2000, 256,  pBW,           2048, 0,   2048};
    d[1]  = {W2,      256, 2000, 256,  pBW+256*2048,  2048, 0,   2048};
    d[2]  = {w12,     256, 256,  256,  pBP,           512,  0,   256};
    d[3]  = {u12,     256, 256,  256,  pBP,           512,  256, 256};
    d[4]  = {u21,     256, 256,  256,  pBP+256*512,   512,  0,   256};
    d[5]  = {w21,     256, 256,  256,  pBP+256*512,   512,  256, 256};
    d[6]  = {v12,     256, 256,  256,  pBV,           256,  0,   256};
    d[7]  = {v21,     256, 256,  256,  pBV+256*256,   256,  0,   256};
    d[8]  = {decompW, 512, 512,  512,  pBD,           512,  0,   512};
    d[9]  = {croW,    512, 512,  512,  pBC,           512,  0,   512};
    d[10] = {kern,    1536, 512, 1536, pBK,           512,  0,   512};
    d[11] = {rkern,   1536, 512, 1536, pBK+1536*512,  512,  0,   512};
    d[12] = {rkern+1024, 1536, 512, 512, pBR,         512,  0,   512};
    tp.pre[0] = 0;
    for (int i = 0; i < 13; ++i)
        tp.pre[i+1] = tp.pre[i] + (d[i].N >> 5) * (d[i].Kw >> 5);
    tsplit_batch<<<tp.pre[13], dim3(32, 8)>>>(tp);

    split_inputs<<<(2*4096*256 + 255)/256, 256>>>(inputs);
    fsplit<<<(int)((BU + 255)/256), 256>>>(crohis_tm, pCTh, pCTl, BU);

    // emb = inputs @ W  (z-batched, K padded to 2048)  grid 256
    mma_gemm<0><<<dim3(2,64,2), 256, SMEM_BYTES>>>(
        pINh, pINl, 2048, 4096LL*2048, pBW, (long long)256*2048,
        pEf, 512, 256, pEh, pEl, 2048, nullptr, nullptr, nullptr, 0, -1, 0);
    // S = emb @ [w;u]   (K=512)  grid 256
    mma_gemm<0><<<dim3(2,64,2), 256, SMEM_BYTES>>>(
        pEh, pEl, 512, 0, pBP, (long long)256*512,
        pSf, 256, (long long)BROWS*256, nullptr, nullptr, 512,
        nullptr, nullptr, nullptr, 0, -1, 0);
    // V12 = emb2 @ v12, V21 = emb1 @ v21  (K=256)  grid 256
    mma_gemm<0><<<dim3(2,64,2), 256, SMEM_BYTES>>>(
        pEh+256, pEl+256, 512, -256, pBV, (long long)256*256,
        pVf, 256, (long long)BROWS*256, nullptr, nullptr, 256,
        nullptr, nullptr, nullptr, 0, -1, 0);
    // attention + crohis_new (second half of d_out)
    attn_kernel<<<BROWS, 256>>>(crohis_tm, out + BU);
    // cro = tanh(crohis_tm @ decompW + decompB)  grid 256
    mma_gemm<2><<<dim3(4,64,1), 256, SMEM_BYTES>>>(
        pCTh, pCTl, 512, 0, pBD, 0,
        nullptr, 512, 0, pCRh, pCRl, 512, decompB, decompB, nullptr, 0, -1, 0);
    // h_prev = h_tm1 + tanh(cro @ croW + croB)  grid 256
    mma_gemm<3><<<dim3(4,64,1), 256, SMEM_BYTES>>>(
        pCRh, pCRl, 512, 0, pBC, 0,
        pHP, 512, 0, pXHh + BU, pXHl + BU, 512, croB, croB, h_tm1, 512, -1, 0);
    // mx = x @ kernel + bias ; mi(first 1024 cols) = h_prev @ rkern  grid 1280
    mma_gemm<1><<<dim3(12,64,2), 256, SMEM_BYTES>>>(
        pXHh, pXHl, 512, BU, pBK, (long long)1536*512,
        pMXI, 1536, (long long)BROWS*1536, nullptr, nullptr, 512,
        bias, pZB, nullptr, 0, 1, 8);
    // r gate, rh = r*h_prev (hi/lo)
    rgate_kernel<<<(BROWS*UDIM + 255)/256, 256>>>();
    // mh = rh @ rkern[:, 2U:]  grid 256
    mma_gemm<0><<<dim3(4,64,1), 256, SMEM_BYTES>>>(
        pRHh, pRHl, 512, 0, pBR, 0,
        pMH, 512, 0, nullptr, nullptr, 512, nullptr, nullptr, nullptr, 0, -1, 0);
    // GRU combine -> h (first half of d_out)
    gru_kernel<<<(BROWS*UDIM + 255)/256, 256>>>(out);
}

// round 14
// speedup vs baseline: 1.4545x; 1.1740x over previous
#include <cuda_runtime.h>
#include <cuda_fp16.h>
#include <math.h>
#include <stdint.h>

namespace {
constexpr int BROWS  = 4096;
constexpr int UDIM   = 512;
constexpr int THREEU = 1536;
constexpr long long BU = (long long)BROWS * UDIM;
// CTA tile 64x128, k-chunk 64. Rows 144B (128B data + 16 pad).
// Stage: Ah(64r) 9216 + Al(64r) 9216 + Bh(128r) 18432 = 36864
constexpr int ROWB        = 144;
constexpr int STAGE_BYTES = 36864;
constexpr int SMEM_BYTES  = 2 * STAGE_BYTES;   // 73728 -> 2 CTAs/SM
}

// ------------------------------ PTX helpers --------------------------------
__device__ __forceinline__ void cp16(uint32_t s, const void* g) {
    asm volatile("cp.async.cg.shared.global [%0], [%1], 16;" :: "r"(s), "l"(g));
}
__device__ __forceinline__ uint32_t smem_u32(const void* p) {
    uint32_t a;
    asm("{ .reg .u64 t; cvta.to.shared.u64 t, %1; cvt.u32.u64 %0, t; }" : "=r"(a) : "l"(p));
    return a;
}
#define CP_COMMIT() asm volatile("cp.async.commit_group;" ::: "memory")
#define CP_WAIT0()  asm volatile("cp.async.wait_group 0;" ::: "memory")
#define LDSM4(r0,r1,r2,r3,a) \
    asm volatile("ldmatrix.sync.aligned.m8n8.x4.shared.b16 {%0,%1,%2,%3}, [%4];" \
        : "=r"(r0),"=r"(r1),"=r"(r2),"=r"(r3) : "r"(a))
#define MMA(d,a,b) \
    asm volatile("mma.sync.aligned.m16n8k16.row.col.f32.f16.f16.f32 " \
        "{%0,%1,%2,%3},{%4,%5,%6,%7},{%8,%9},{%0,%1,%2,%3};" \
        : "+f"((d)[0]),"+f"((d)[1]),"+f"((d)[2]),"+f"((d)[3]) \
        : "r"((a)[0]),"r"((a)[1]),"r"((a)[2]),"r"((a)[3]),"r"((b)[0]),"r"((b)[1]))

__device__ __forceinline__ uint32_t packhl(float a, float b, bool lo) {
    if (lo) {
        a -= __half2float(__float2half_rn(a));
        b -= __half2float(__float2half_rn(b));
    }
    __half2 h2 = __floats2half2_rn(a, b);
    return *(uint32_t*)&h2;
}

// ------------------------------ scratch ------------------------------------
__device__ __half g_BW[2*256*2048];
__device__ __half g_BP[2*256*512];
__device__ __half g_BV[2*256*256];
__device__ __half g_BD[512*512];
__device__ __half g_BC[512*512];
__device__ __half g_BK[2*1536*512];
__device__ __half g_BR[512*512];
__device__ float  g_embf[4096*512];
__device__ __half g_embh[4096*512],  g_embl[4096*512];
__device__ float  g_Sf[2*4096*256],  g_Vf[2*4096*256];
__device__ __half g_xhh[2*4096*512], g_xhl[2*4096*512];
__device__ float  g_hprev[4096*512];
__device__ __half g_croh[4096*512],  g_crol[4096*512];
__device__ float  g_mxi[2LL*4096*1536];
__device__ __half g_rhh[4096*512],   g_rhl[4096*512];
__device__ float  g_mh[4096*512];
__device__ float  g_zbias[1536];

// ------------------- batched transpose + fp16 convert (weights) -------------
struct TDesc {
    const float* src; int sld, Kr, N;
    __half* dh; int dld, ko, Kw;
};
struct TPack { TDesc d[13]; int pre[14]; };

__global__ void tsplit_batch(TPack p)
{
    __shared__ float t[32][33];
    int blk = blockIdx.x;
    int di = 0;
    while (di < 13 && blk >= p.pre[di + 1]) ++di;
    const TDesc& D = p.d[di];
    int local = blk - p.pre[di];
    int nx = D.N >> 5;
    int ty_t = local / nx, tx_t = local % nx;
    int kt = ty_t * 32, nt = tx_t * 32;
    int tx = threadIdx.x, ty = threadIdx.y;    // (32,8)
    #pragma unroll
    for (int i = 0; i < 32; i += 8) {
        int k = kt + ty + i, n = nt + tx;
        t[ty + i][tx] = (k < D.Kr && n < D.N) ? D.src[(size_t)k * D.sld + n] : 0.f;
    }
    __syncthreads();
    #pragma unroll
    for (int i = 0; i < 32; i += 8) {
        int n = nt + ty + i, k = kt + tx;
        if (n < D.N && k < D.Kw)
            D.dh[(size_t)n * D.dld + D.ko + k] = __float2half_rn(t[tx][ty + i]);
    }
}

// ------------------------------ mma.sync GEMM -------------------------------
// C = (Ah+Al) @ B^T  (A fp16 hi/lo, B single fp16; 2 MMAs/tile).
// AF32: A source is fp32; convert to hi/lo in-register during the load phase.
// CTA 64x128, 8 warps (2m x 4n), warp tile 32x32, k-chunk 64, 2-stage, 2 CTAs/SM.
// EPI: 0 store, 1 +bias, 2 tanh(+bias), 3 add+tanh(+bias)
template <int EPI, bool AF32>
__global__ void __launch_bounds__(256, 2)
mma_gemm(const void* Asrc_, const __half* Alo_, long long lda, long long aZ, int Kvalid,
         const __half* Bhi_, long long bZ,
         float* C, long long ldc, long long cZ, __half* Chi, __half* Clo,
         int K, const float* bias0, const float* bias1,
         const float* add, long long ldadd, int skipZ, int skipXfrom)
{
    const int z = blockIdx.z, tn = blockIdx.x, tm = blockIdx.y;
    if (z == skipZ && tn >= skipXfrom) return;

    extern __shared__ __align__(16) uint8_t smem[];
    char* const tp = (char*)smem;

    const int tid = threadIdx.x, wid = tid >> 5, lane = tid & 31;
    const int m0 = tm * 64, n0 = tn * 128;
    const int wm = wid & 1, wn = wid >> 1;       // 2m x 4n, warp tile 32x32

    const float*  Af32 = AF32 ? ((const float*)Asrc_ + z * aZ) : nullptr;
    const __half* Ahi  = AF32 ? nullptr : ((const __half*)Asrc_ + z * aZ);
    const __half* Alo  = AF32 ? nullptr : (Alo_ + z * aZ);
    const __half* Bhi  = Bhi_ + z * bZ;
    if (C)   C   += z * cZ;
    if (Chi) { Chi += z * cZ; Clo += z * cZ; }
    const float* biasp = (z == 0) ? bias0 : bias1;

    const uint32_t sbase = smem_u32(smem);
    // per stage: Ah +0 (64r), Al +9216 (64r), Bh +18432 (128r) ; rows 144B
    uint32_t aB_[2], bB_[2], sS_[2];
    #pragma unroll
    for (int s = 0; s < 2; ++s) {
        sS_[s] = sbase + s * STAGE_BYTES;
        aB_[s] = sS_[s] + (wm * 32 + (lane & 15)) * ROWB + (lane >> 4) * 16;
        bB_[s] = sS_[s] + 18432
               + (wn * 32 + (lane & 7) + ((lane >> 4) & 1) * 8) * ROWB
               + ((lane >> 3) & 1) * 16;
    }
    const int ra = tid >> 2, sega = tid & 3;     // A: 64 rows x 4 segs (16 elems)
    const int rb = tid >> 1, hb = tid & 1;       // B: 128 rows x 2 halves (32 elems)

    float acc[2][4][4];
    #pragma unroll
    for (int a = 0; a < 2; ++a)
        #pragma unroll
        for (int b = 0; b < 4; ++b)
            #pragma unroll
            for (int c = 0; c < 4; ++c) acc[a][b][c] = 0.f;

    const int nch = K / 64;

    auto issue = [&](int cc) {
        const int ko = cc * 64, st = cc & 1;
        const uint32_t sg = sS_[st];
        char* const sp = tp + st * STAGE_BYTES;
        // ---- A (hi/lo) ----
        if (AF32) {
            const int kb = ko + sega * 16;
            const float* ap = Af32 + (size_t)(m0 + ra) * lda + kb;
            float f[16];
            if (kb + 16 <= Kvalid) {
                #pragma unroll
                for (int j = 0; j < 4; ++j) *(float4*)&f[j*4] = *(const float4*)(ap + j*4);
            } else {
                #pragma unroll
                for (int e = 0; e < 16; ++e) f[e] = (kb + e < Kvalid) ? ap[e] : 0.f;
            }
            uint32_t hw[8], lw[8];
            #pragma unroll
            for (int j = 0; j < 8; ++j) {
                hw[j] = packhl(f[2*j], f[2*j+1], false);
                lw[j] = packhl(f[2*j], f[2*j+1], true);
            }
            const int so = ra * ROWB + sega * 32;
            *(uint4*)(sp + so)          = make_uint4(hw[0], hw[1], hw[2], hw[3]);
            *(uint4*)(sp + so + 16)     = make_uint4(hw[4], hw[5], hw[6], hw[7]);
            *(uint4*)(sp + 9216 + so)      = make_uint4(lw[0], lw[1], lw[2], lw[3]);
            *(uint4*)(sp + 9216 + so + 16) = make_uint4(lw[4], lw[5], lw[6], lw[7]);
        } else {
            const uint32_t so = ra * ROWB + sega * 32;
            const size_t ao = (size_t)(m0 + ra) * lda + ko + sega * 16;
            cp16(sg + so,             Ahi + ao);
            cp16(sg + so + 16,        Ahi + ao + 8);
            cp16(sg + 9216 + so,      Alo + ao);
            cp16(sg + 9216 + so + 16, Alo + ao + 8);
        }
        // ---- B ----
        {
            const uint32_t so = rb * ROWB + hb * 64;
            const __half* bp = Bhi + (size_t)(n0 + rb) * K + ko + hb * 32;
            cp16(sg + 18432 + so,      bp);
            cp16(sg + 18432 + so + 16, bp + 8);
            cp16(sg + 18432 + so + 32, bp + 16);
            cp16(sg + 18432 + so + 48, bp + 24);
        }
        CP_COMMIT();
    };

    issue(0);
    for (int cc = 0; cc < nch; ++cc) {
        const int st = cc & 1;
        CP_WAIT0();
        __syncthreads();
        if (cc + 1 < nch) issue(cc + 1);
        const uint32_t aB = aB_[st], bB = bB_[st];
        #pragma unroll
        for (int s = 0; s < 4; ++s) {
            uint32_t bh[4][2];
            #pragma unroll
            for (int np = 0; np < 2; ++np)
                LDSM4(bh[2*np][0], bh[2*np][1], bh[2*np+1][0], bh[2*np+1][1],
                      bB + np * 16 * ROWB + s * 32);
            #pragma unroll
            for (int mt = 0; mt < 2; ++mt) {
                uint32_t ah[4], al[4];
                LDSM4(ah[0], ah[1], ah[2], ah[3], aB + mt * 16 * ROWB + s * 32);
                LDSM4(al[0], al[1], al[2], al[3], aB + 9216 + mt * 16 * ROWB + s * 32);
                #pragma unroll
                for (int nt = 0; nt < 4; ++nt) {
                    MMA(acc[mt][nt], ah, bh[nt]);
                    MMA(acc[mt][nt], al, bh[nt]);
                }
            }
        }
        __syncthreads();
    }

    // ------------------------------ epilogue --------------------------------
    const int tig = lane & 3, gid = lane >> 2;
    #pragma unroll
    for (int mt = 0; mt < 2; ++mt) {
        #pragma unroll
        for (int half = 0; half < 2; ++half) {
            const int row = m0 + wm * 32 + mt * 16 + gid + half * 8;
            #pragma unroll
            for (int nt = 0; nt < 4; ++nt) {
                const int col = n0 + wn * 32 + nt * 8 + 2 * tig;
                float x0 = acc[mt][nt][half * 2 + 0];
                float x1 = acc[mt][nt][half * 2 + 1];
                if (EPI == 1)      { x0 += biasp[col]; x1 += biasp[col + 1]; }
                else if (EPI == 2) { x0 = tanhf(x0 + biasp[col]); x1 = tanhf(x1 + biasp[col + 1]); }
                else if (EPI == 3) {
                    x0 = add[(size_t)row * ldadd + col]     + tanhf(x0 + biasp[col]);
                    x1 = add[(size_t)row * ldadd + col + 1] + tanhf(x1 + biasp[col + 1]);
                }
                if (C) *(float2*)(C + (size_t)row * ldc + col) = make_float2(x0, x1);
                if (Chi) {
                    *(uint32_t*)(Chi + (size_t)row * ldc + col) = packhl(x0, x1, false);
                    *(uint32_t*)(Clo + (size_t)row * ldc + col) = packhl(x0, x1, true);
                }
            }
        }
    }
}

// ------------------------------ attention + crohis_new ----------------------
__global__ void __launch_bounds__(256)
attn_kernel(const float* __restrict__ crohis_tm, float* __restrict__ out_crohis)
{
    __shared__ float red[256];
    const int row = blockIdx.x, c = threadIdx.x;
    const float* emb = g_embf + (long long)row * 512;
    #pragma unroll
    for (int side = 0; side < 2; side++) {
        const float* S = g_Sf + (long long)side * (BROWS*256) + (long long)row * 256;
        const float* V = g_Vf + (long long)side * (BROWS*256) + (long long)row * 256;
        float l = tanhf(S[c]) * V[c];
        red[c] = l; __syncthreads();
        #pragma unroll
        for (int s = 128; s > 0; s >>= 1) { if (c < s) red[c] = fmaxf(red[c], red[c+s]); __syncthreads(); }
        float m = red[0]; __syncthreads();
        float e = __expf(l - m);
        red[c] = e; __syncthreads();
        #pragma unroll
        for (int s = 128; s > 0; s >>= 1) { if (c < s) red[c] += red[c+s]; __syncthreads(); }
        float ssum = red[0]; __syncthreads();
        int col = side * 256 + c;
        float xv = emb[col] * (e / ssum);
        long long gi = (long long)row * 512 + col;
        __half h = __float2half_rn(xv);
        g_xhh[gi] = h;
        g_xhl[gi] = __float2half_rn(xv - __half2float(h));
        out_crohis[gi] = 0.5f * crohis_tm[gi] + 0.5f * xv;
    }
}

__global__ void rgate_kernel()
{
    int idx = blockIdx.x * blockDim.x + threadIdx.x;
    if (idx >= BROWS * UDIM) return;
    int row = idx >> 9, col = idx & 511;
    const float* mx = g_mxi + (long long)row * THREEU;
    const float* mi = g_mxi + (long long)BROWS * THREEU + (long long)row * THREEU;
    float r = 1.0f / (1.0f + __expf(-(mx[col + 512] + mi[col + 512])));
    float rh = r * g_hprev[idx];
    __half h = __float2half_rn(rh);
    g_rhh[idx] = h;
    g_rhl[idx] = __float2half_rn(rh - __half2float(h));
}

__global__ void gru_kernel(float* __restrict__ h_out)
{
    int idx = blockIdx.x * blockDim.x + threadIdx.x;
    if (idx >= BROWS * UDIM) return;
    int row = idx >> 9, col = idx & 511;
    const float* mx = g_mxi + (long long)row * THREEU;
    const float* mi = g_mxi + (long long)BROWS * THREEU + (long long)row * THREEU;
    float z  = 1.0f / (1.0f + __expf(-(mx[col] + mi[col])));
    float hp = g_hprev[idx];
    float hh = tanhf(mx[col + 1024] + g_mh[idx]);
    h_out[idx] = z * hp + (1.0f - z) * hh;
}

// ------------------------------ launch --------------------------------------
extern "C" void kernel_launch(void* const* d_in, const int* in_sizes, int n_in,
                              void* d_out, int out_size)
{
    const float* inputs    = (const float*)d_in[0];
    const float* h_tm1     = (const float*)d_in[1];
    const float* crohis_tm = (const float*)d_in[2];
    const float* W1   = (const float*)d_in[3];
    const float* W2   = (const float*)d_in[4];
    const float* w12  = (const float*)d_in[5];
    const float* u12  = (const float*)d_in[6];
    const float* v12  = (const float*)d_in[7];
    const float* w21  = (const float*)d_in[8];
    const float* u21  = (const float*)d_in[9];
    const float* v21  = (const float*)d_in[10];
    const float* croW = (const float*)d_in[11];
    const float* croB = (const float*)d_in[12];
    const float* decompW = (const float*)d_in[13];
    const float* decompB = (const float*)d_in[14];
    const float* kern  = (const float*)d_in[15];
    const float* rkern = (const float*)d_in[16];
    const float* bias  = (const float*)d_in[17];
    float* out = (float*)d_out;

    static bool attr_done = false;
    if (!attr_done) {
        cudaFuncSetAttribute(mma_gemm<0,true>,  cudaFuncAttributeMaxDynamicSharedMemorySize, SMEM_BYTES);
        cudaFuncSetAttribute(mma_gemm<0,false>, cudaFuncAttributeMaxDynamicSharedMemorySize, SMEM_BYTES);
        cudaFuncSetAttribute(mma_gemm<1,false>, cudaFuncAttributeMaxDynamicSharedMemorySize, SMEM_BYTES);
        cudaFuncSetAttribute(mma_gemm<2,true>,  cudaFuncAttributeMaxDynamicSharedMemorySize, SMEM_BYTES);
        cudaFuncSetAttribute(mma_gemm<3,false>, cudaFuncAttributeMaxDynamicSharedMemorySize, SMEM_BYTES);
        cudaFuncSetAttribute(mma_gemm<0,true>,  cudaFuncAttributePreferredSharedMemoryCarveout, 100);
        cudaFuncSetAttribute(mma_gemm<0,false>, cudaFuncAttributePreferredSharedMemoryCarveout, 100);
        cudaFuncSetAttribute(mma_gemm<1,false>, cudaFuncAttributePreferredSharedMemoryCarveout, 100);
        cudaFuncSetAttribute(mma_gemm<2,true>,  cudaFuncAttributePreferredSharedMemoryCarveout, 100);
        cudaFuncSetAttribute(mma_gemm<3,false>, cudaFuncAttributePreferredSharedMemoryCarveout, 100);
        attr_done = true;
    }

    __half *pBW,*pBP,*pBV,*pBD,*pBC,*pBK,*pBR,
           *pEh,*pEl,*pXHh,*pXHl,*pCRh,*pCRl,*pRHh,*pRHl;
    float *pEf,*pSf,*pVf,*pHP,*pMXI,*pMH,*pZB;
    cudaGetSymbolAddress((void**)&pBW,g_BW);
    cudaGetSymbolAddress((void**)&pBP,g_BP);
    cudaGetSymbolAddress((void**)&pBV,g_BV);
    cudaGetSymbolAddress((void**)&pBD,g_BD);
    cudaGetSymbolAddress((void**)&pBC,g_BC);
    cudaGetSymbolAddress((void**)&pBK,g_BK);
    cudaGetSymbolAddress((void**)&pBR,g_BR);
    cudaGetSymbolAddress((void**)&pEf,g_embf);
    cudaGetSymbolAddress((void**)&pEh,g_embh); cudaGetSymbolAddress((void**)&pEl,g_embl);
    cudaGetSymbolAddress((void**)&pSf,g_Sf);   cudaGetSymbolAddress((void**)&pVf,g_Vf);
    cudaGetSymbolAddress((void**)&pXHh,g_xhh); cudaGetSymbolAddress((void**)&pXHl,g_xhl);
    cudaGetSymbolAddress((void**)&pHP,g_hprev);
    cudaGetSymbolAddress((void**)&pCRh,g_croh); cudaGetSymbolAddress((void**)&pCRl,g_crol);
    cudaGetSymbolAddress((void**)&pMXI,g_mxi);
    cudaGetSymbolAddress((void**)&pRHh,g_rhh); cudaGetSymbolAddress((void**)&pRHl,g_rhl);
    cudaGetSymbolAddress((void**)&pMH,g_mh);   cudaGetSymbolAddress((void**)&pZB,g_zbias);

    // batched weight transpose+convert (one launch)
    TPack tp;
    TDesc* d = tp.d;
    d[0]  = {W1,      256, 2000, 256,  pBW,           2048, 0,   2048};
    d[1]  = {W2,      256, 2000, 256,  pBW+256*2048,  2048, 0,   2048};
    d[2]  = {w12,     256, 256,  256,  pBP,           512,  0,   256};
    d[3]  = {u12,     256, 256,  256,  pBP,           512,  256, 256};
    d[4]  = {u21,     256, 256,  256,  pBP+256*512,   512,  0,   256};
    d[5]  = {w21,     256, 256,  256,  pBP+256*512,   512,  256, 256};
    d[6]  = {v12,     256, 256,  256,  pBV,           256,  0,   256};
    d[7]  = {v21,     256, 256,  256,  pBV+256*256,   256,  0,   256};
    d[8]  = {decompW, 512, 512,  512,  pBD,           512,  0,   512};
    d[9]  = {croW,    512, 512,  512,  pBC,           512,  0,   512};
    d[10] = {kern,    1536, 512, 1536, pBK,           512,  0,   512};
    d[11] = {rkern,   1536, 512, 1536, pBK+1536*512,  512,  0,   512};
    d[12] = {rkern+1024, 1536, 512, 512, pBR,         512,  0,   512};
    tp.pre[0] = 0;
    for (int i = 0; i < 13; ++i)
        tp.pre[i+1] = tp.pre[i] + (d[i].N >> 5) * (d[i].Kw >> 5);
    tsplit_batch<<<tp.pre[13], dim3(32, 8)>>>(tp);

    // emb = inputs @ W  (fp32 A converted in-kernel; K padded to 2048)  grid 256
    mma_gemm<0,true><<<dim3(2,64,2), 256, SMEM_BYTES>>>(
        inputs, nullptr, 4000, 2000, 2000, pBW, (long long)256*2048,
        pEf, 512, 256, pEh, pEl, 2048, nullptr, nullptr, nullptr, 0, -1, 0);
    // S = emb @ [w;u]   (K=512)  grid 256
    mma_gemm<0,false><<<dim3(2,64,2), 256, SMEM_BYTES>>>(
        pEh, pEl, 512, 0, 512, pBP, (long long)256*512,
        pSf, 256, (long long)BROWS*256, nullptr, nullptr, 512,
        nullptr, nullptr, nullptr, 0, -1, 0);
    // V12 = emb2 @ v12, V21 = emb1 @ v21  (K=256)  grid 256
    mma_gemm<0,false><<<dim3(2,64,2), 256, SMEM_BYTES>>>(
        pEh+256, pEl+256, 512, -256, 256, pBV, (long long)256*256,
        pVf, 256, (long long)BROWS*256, nullptr, nullptr, 256,
        nullptr, nullptr, nullptr, 0, -1, 0);
    // attention + crohis_new (second half of d_out)
    attn_kernel<<<BROWS, 256>>>(crohis_tm, out + BU);
    // cro = tanh(crohis_tm @ decompW + decompB)  (fp32 A in-kernel)  grid 256
    mma_gemm<2,true><<<dim3(4,64,1), 256, SMEM_BYTES>>>(
        crohis_tm, nullptr, 512, 0, 512, pBD, 0,
        nullptr, 512, 0, pCRh, pCRl, 512, decompB, decompB, nullptr, 0, -1, 0);
    // h_prev = h_tm1 + tanh(cro @ croW + croB)  grid 256
    mma_gemm<3,false><<<dim3(4,64,1), 256, SMEM_BYTES>>>(
        pCRh, pCRl, 512, 0, 512, pBC, 0,
        pHP, 512, 0, pXHh + BU, pXHl + BU, 512, croB, croB, h_tm1, 512, -1, 0);
    // mx = x @ kernel + bias ; mi(first 1024 cols) = h_prev @ rkern  grid 1280
    mma_gemm<1,false><<<dim3(12,64,2), 256, SMEM_BYTES>>>(
        pXHh, pXHl, 512, BU, 512, pBK, (long long)1536*512,
        pMXI, 1536, (long long)BROWS*1536, nullptr, nullptr, 512,
        bias, pZB, nullptr, 0, 1, 8);
    // r gate, rh = r*h_prev (hi/lo)
    rgate_kernel<<<(BROWS*UDIM + 255)/256, 256>>>();
    // mh = rh @ rkern[:, 2U:]  grid 256
    mma_gemm<0,false><<<dim3(4,64,1), 256, SMEM_BYTES>>>(
        pRHh, pRHl, 512, 0, 512, pBR, 0,
        pMH, 512, 0, nullptr, nullptr, 512, nullptr, nullptr, nullptr, 0, -1, 0);
    // GRU combine -> h (first half of d_out)
    gru_kernel<<<(BROWS*UDIM + 255)/256, 256>>>(out);
}

// round 15
// speedup vs baseline: 1.5075x; 1.0364x over previous
#include <cuda_runtime.h>
#include <cuda_fp16.h>
#include <math.h>
#include <stdint.h>

namespace {
constexpr int BROWS  = 4096;
constexpr int UDIM   = 512;
constexpr int THREEU = 1536;
constexpr long long BU = (long long)BROWS * UDIM;
// CTA tile 64x128, k-chunk 64. Rows 144B (128B data + 16 pad).
// Stage: Ah(64r) 9216 + Al(64r) 9216 + Bh(128r) 18432 = 36864
constexpr int ROWB        = 144;
constexpr int STAGE_BYTES = 36864;
constexpr int SMEM_BYTES  = 2 * STAGE_BYTES;   // 73728 -> 2 CTAs/SM
}

// ------------------------------ PTX helpers --------------------------------
__device__ __forceinline__ void cp16(uint32_t s, const void* g) {
    asm volatile("cp.async.cg.shared.global [%0], [%1], 16;" :: "r"(s), "l"(g));
}
__device__ __forceinline__ uint32_t smem_u32(const void* p) {
    uint32_t a;
    asm("{ .reg .u64 t; cvta.to.shared.u64 t, %1; cvt.u32.u64 %0, t; }" : "=r"(a) : "l"(p));
    return a;
}
#define CP_COMMIT() asm volatile("cp.async.commit_group;" ::: "memory")
#define CP_WAIT0()  asm volatile("cp.async.wait_group 0;" ::: "memory")
#define LDSM4(r0,r1,r2,r3,a) \
    asm volatile("ldmatrix.sync.aligned.m8n8.x4.shared.b16 {%0,%1,%2,%3}, [%4];" \
        : "=r"(r0),"=r"(r1),"=r"(r2),"=r"(r3) : "r"(a))
#define MMA(d,a,b) \
    asm volatile("mma.sync.aligned.m16n8k16.row.col.f32.f16.f16.f32 " \
        "{%0,%1,%2,%3},{%4,%5,%6,%7},{%8,%9},{%0,%1,%2,%3};" \
        : "+f"((d)[0]),"+f"((d)[1]),"+f"((d)[2]),"+f"((d)[3]) \
        : "r"((a)[0]),"r"((a)[1]),"r"((a)[2]),"r"((a)[3]),"r"((b)[0]),"r"((b)[1]))

__device__ __forceinline__ uint32_t packhl(float a, float b, bool lo) {
    if (lo) {
        a -= __half2float(__float2half_rn(a));
        b -= __half2float(__float2half_rn(b));
    }
    __half2 h2 = __floats2half2_rn(a, b);
    return *(uint32_t*)&h2;
}

// ------------------------------ scratch ------------------------------------
__device__ __half g_BW[2*256*2048];
__device__ __half g_BP[2*256*512];
__device__ __half g_BV[2*256*256];
__device__ __half g_BD[512*512];
__device__ __half g_BC[512*512];
__device__ __half g_BK[2*1536*512];
__device__ __half g_BR[512*512];
__device__ float  g_embf[4096*512];
__device__ __half g_embh[4096*512],  g_embl[4096*512];
__device__ float  g_Sf[2*4096*256],  g_Vf[2*4096*256];
__device__ __half g_xhh[2*4096*512], g_xhl[2*4096*512];
__device__ float  g_hprev[4096*512];
__device__ __half g_croh[4096*512],  g_crol[4096*512];
__device__ float  g_mxi[2LL*4096*1536];
__device__ __half g_rhh[4096*512],   g_rhl[4096*512];
__device__ float  g_mh[4096*512];
__device__ float  g_zbias[1536];

// ------------------- batched transpose + fp16 convert (weights) -------------
struct TDesc {
    const float* src; int sld, Kr, N;
    __half* dh; int dld, ko, Kw;
};
struct TPack { TDesc d[13]; int pre[14]; };

__global__ void tsplit_batch(TPack p)
{
    __shared__ float t[32][33];
    int blk = blockIdx.x;
    int di = 0;
    while (di < 13 && blk >= p.pre[di + 1]) ++di;
    const TDesc& D = p.d[di];
    int local = blk - p.pre[di];
    int nx = D.N >> 5;
    int ty_t = local / nx, tx_t = local % nx;
    int kt = ty_t * 32, nt = tx_t * 32;
    int tx = threadIdx.x, ty = threadIdx.y;    // (32,8)
    #pragma unroll
    for (int i = 0; i < 32; i += 8) {
        int k = kt + ty + i, n = nt + tx;
        t[ty + i][tx] = (k < D.Kr && n < D.N) ? D.src[(size_t)k * D.sld + n] : 0.f;
    }
    __syncthreads();
    #pragma unroll
    for (int i = 0; i < 32; i += 8) {
        int n = nt + ty + i, k = kt + tx;
        if (n < D.N && k < D.Kw)
            D.dh[(size_t)n * D.dld + D.ko + k] = __float2half_rn(t[tx][ty + i]);
    }
}

// ------------------------------ mma.sync GEMM -------------------------------
// C = (Ah+Al) @ B^T  (A fp16 hi/lo, B single fp16; 2 MMAs/tile).
// AF32: A fp32 source, register-prefetched one chunk ahead, converted at STS.
// CTA 64x128, 8 warps (2m x 4n), warp tile 32x32, k-chunk 64, 2-stage, 2 CTAs/SM.
// EPI: 0 store, 1 +bias, 2 tanh(+bias), 3 add+tanh(+bias)
template <int EPI, bool AF32>
__global__ void __launch_bounds__(256, 2)
mma_gemm(const void* Asrc_, const __half* Alo_, long long lda, long long aZ, int Kvalid,
         const __half* Bhi_, long long bZ,
         float* C, long long ldc, long long cZ, __half* Chi, __half* Clo,
         int K, const float* bias0, const float* bias1,
         const float* add, long long ldadd, int skipZ, int skipXfrom)
{
    const int z = blockIdx.z, tn = blockIdx.x, tm = blockIdx.y;
    if (z == skipZ && tn >= skipXfrom) return;

    extern __shared__ __align__(16) uint8_t smem[];
    char* const tp = (char*)smem;

    const int tid = threadIdx.x, wid = tid >> 5, lane = tid & 31;
    const int m0 = tm * 64, n0 = tn * 128;
    const int wm = wid & 1, wn = wid >> 1;       // 2m x 4n, warp tile 32x32

    const float*  Af32 = AF32 ? ((const float*)Asrc_ + z * aZ) : nullptr;
    const __half* Ahi  = AF32 ? nullptr : ((const __half*)Asrc_ + z * aZ);
    const __half* Alo  = AF32 ? nullptr : (Alo_ + z * aZ);
    const __half* Bhi  = Bhi_ + z * bZ;
    if (C)   C   += z * cZ;
    if (Chi) { Chi += z * cZ; Clo += z * cZ; }
    const float* biasp = (z == 0) ? bias0 : bias1;

    const uint32_t sbase = smem_u32(smem);
    uint32_t aB_[2], bB_[2], sS_[2];
    #pragma unroll
    for (int s = 0; s < 2; ++s) {
        sS_[s] = sbase + s * STAGE_BYTES;
        aB_[s] = sS_[s] + (wm * 32 + (lane & 15)) * ROWB + (lane >> 4) * 16;
        bB_[s] = sS_[s] + 18432
               + (wn * 32 + (lane & 7) + ((lane >> 4) & 1) * 8) * ROWB
               + ((lane >> 3) & 1) * 16;
    }
    const int ra = tid >> 2, sega = tid & 3;     // A: 64 rows x 4 segs (16 elems)
    const int rb = tid >> 1, hb = tid & 1;       // B: 128 rows x 2 halves (32 elems)

    float acc[2][4][4];
    #pragma unroll
    for (int a = 0; a < 2; ++a)
        #pragma unroll
        for (int b = 0; b < 4; ++b)
            #pragma unroll
            for (int c = 0; c < 4; ++c) acc[a][b][c] = 0.f;

    const int nch = K / 64;
    float fA[16];

    auto ldgA = [&](int cc) {                    // AF32: prefetch fp32 A to regs
        const int kb = cc * 64 + sega * 16;
        const float* ap = Af32 + (size_t)(m0 + ra) * lda + kb;
        if (kb + 16 <= Kvalid) {
            #pragma unroll
            for (int j = 0; j < 4; ++j) *(float4*)&fA[j*4] = *(const float4*)(ap + j*4);
        } else {
            #pragma unroll
            for (int e = 0; e < 16; ++e) fA[e] = (kb + e < Kvalid) ? ap[e] : 0.f;
        }
    };
    auto stsA = [&](int cc) {                    // AF32: convert + STS into stage
        char* const sp = tp + (cc & 1) * STAGE_BYTES;
        uint32_t hw[8], lw[8];
        #pragma unroll
        for (int j = 0; j < 8; ++j) {
            hw[j] = packhl(fA[2*j], fA[2*j+1], false);
            lw[j] = packhl(fA[2*j], fA[2*j+1], true);
        }
        const int so = ra * ROWB + sega * 32;
        *(uint4*)(sp + so)             = make_uint4(hw[0], hw[1], hw[2], hw[3]);
        *(uint4*)(sp + so + 16)        = make_uint4(hw[4], hw[5], hw[6], hw[7]);
        *(uint4*)(sp + 9216 + so)      = make_uint4(lw[0], lw[1], lw[2], lw[3]);
        *(uint4*)(sp + 9216 + so + 16) = make_uint4(lw[4], lw[5], lw[6], lw[7]);
    };
    auto issueB = [&](int cc) {                  // B via cp.async (and A if !AF32)
        const int ko = cc * 64;
        const uint32_t sg = sS_[cc & 1];
        if (!AF32) {
            const uint32_t so = ra * ROWB + sega * 32;
            const size_t ao = (size_t)(m0 + ra) * lda + ko + sega * 16;
            cp16(sg + so,             Ahi + ao);
            cp16(sg + so + 16,        Ahi + ao + 8);
            cp16(sg + 9216 + so,      Alo + ao);
            cp16(sg + 9216 + so + 16, Alo + ao + 8);
        }
        const uint32_t so = rb * ROWB + hb * 64;
        const __half* bp = Bhi + (size_t)(n0 + rb) * K + ko + hb * 32;
        cp16(sg + 18432 + so,      bp);
        cp16(sg + 18432 + so + 16, bp + 8);
        cp16(sg + 18432 + so + 32, bp + 16);
        cp16(sg + 18432 + so + 48, bp + 24);
        CP_COMMIT();
    };

    if (AF32) ldgA(0);
    issueB(0);
    for (int cc = 0; cc < nch; ++cc) {
        const int st = cc & 1;
        if (AF32) stsA(cc);
        CP_WAIT0();
        __syncthreads();
        if (cc + 1 < nch) {
            issueB(cc + 1);
            if (AF32) ldgA(cc + 1);
        }
        const uint32_t aB = aB_[st], bB = bB_[st];
        #pragma unroll
        for (int s = 0; s < 4; ++s) {
            uint32_t bh[4][2];
            #pragma unroll
            for (int np = 0; np < 2; ++np)
                LDSM4(bh[2*np][0], bh[2*np][1], bh[2*np+1][0], bh[2*np+1][1],
                      bB + np * 16 * ROWB + s * 32);
            #pragma unroll
            for (int mt = 0; mt < 2; ++mt) {
                uint32_t ah[4], al[4];
                LDSM4(ah[0], ah[1], ah[2], ah[3], aB + mt * 16 * ROWB + s * 32);
                LDSM4(al[0], al[1], al[2], al[3], aB + 9216 + mt * 16 * ROWB + s * 32);
                #pragma unroll
                for (int nt = 0; nt < 4; ++nt) {
                    MMA(acc[mt][nt], ah, bh[nt]);
                    MMA(acc[mt][nt], al, bh[nt]);
                }
            }
        }
        // no trailing sync: next iteration's wait+sync orders buffer reuse
    }

    // ------------------------------ epilogue --------------------------------
    const int tig = lane & 3, gid = lane >> 2;
    #pragma unroll
    for (int mt = 0; mt < 2; ++mt) {
        #pragma unroll
        for (int half = 0; half < 2; ++half) {
            const int row = m0 + wm * 32 + mt * 16 + gid + half * 8;
            #pragma unroll
            for (int nt = 0; nt < 4; ++nt) {
                const int col = n0 + wn * 32 + nt * 8 + 2 * tig;
                float x0 = acc[mt][nt][half * 2 + 0];
                float x1 = acc[mt][nt][half * 2 + 1];
                if (EPI == 1)      { x0 += biasp[col]; x1 += biasp[col + 1]; }
                else if (EPI == 2) { x0 = tanhf(x0 + biasp[col]); x1 = tanhf(x1 + biasp[col + 1]); }
                else if (EPI == 3) {
                    x0 = add[(size_t)row * ldadd + col]     + tanhf(x0 + biasp[col]);
                    x1 = add[(size_t)row * ldadd + col + 1] + tanhf(x1 + biasp[col + 1]);
                }
                if (C) *(float2*)(C + (size_t)row * ldc + col) = make_float2(x0, x1);
                if (Chi) {
                    *(uint32_t*)(Chi + (size_t)row * ldc + col) = packhl(x0, x1, false);
                    *(uint32_t*)(Clo + (size_t)row * ldc + col) = packhl(x0, x1, true);
                }
            }
        }
    }
}

// --------------- attention + crohis_new (warp per row-side) -----------------
__global__ void __launch_bounds__(256)
attn_kernel(const float* __restrict__ crohis_tm, float* __restrict__ out_crohis)
{
    const int gw   = blockIdx.x * 8 + (threadIdx.x >> 5);  // 0..8191
    const int lane = threadIdx.x & 31;
    const int row = gw >> 1, side = gw & 1;
    const float* S = g_Sf + (long long)side * (BROWS*256) + (long long)row * 256;
    const float* V = g_Vf + (long long)side * (BROWS*256) + (long long)row * 256;

    float l[8];
    float m = -1e30f;
    #pragma unroll
    for (int j = 0; j < 8; ++j) {
        int c = j * 32 + lane;
        l[j] = tanhf(S[c]) * V[c];
        m = fmaxf(m, l[j]);
    }
    #pragma unroll
    for (int o = 16; o > 0; o >>= 1) m = fmaxf(m, __shfl_xor_sync(0xFFFFFFFFu, m, o));
    float ssum = 0.f;
    #pragma unroll
    for (int j = 0; j < 8; ++j) { l[j] = __expf(l[j] - m); ssum += l[j]; }
    #pragma unroll
    for (int o = 16; o > 0; o >>= 1) ssum += __shfl_xor_sync(0xFFFFFFFFu, ssum, o);
    const float inv = 1.f / ssum;

    const float* emb = g_embf + (long long)row * 512;
    #pragma unroll
    for (int j = 0; j < 8; ++j) {
        int col = side * 256 + j * 32 + lane;
        float xv = emb[col] * l[j] * inv;
        long long gi = (long long)row * 512 + col;
        __half h = __float2half_rn(xv);
        g_xhh[gi] = h;
        g_xhl[gi] = __float2half_rn(xv - __half2float(h));
        out_crohis[gi] = 0.5f * crohis_tm[gi] + 0.5f * xv;
    }
}

__global__ void rgate_kernel()
{
    int idx = blockIdx.x * blockDim.x + threadIdx.x;
    if (idx >= BROWS * UDIM) return;
    int row = idx >> 9, col = idx & 511;
    const float* mx = g_mxi + (long long)row * THREEU;
    const float* mi = g_mxi + (long long)BROWS * THREEU + (long long)row * THREEU;
    float r = 1.0f / (1.0f + __expf(-(mx[col + 512] + mi[col + 512])));
    float rh = r * g_hprev[idx];
    __half h = __float2half_rn(rh);
    g_rhh[idx] = h;
    g_rhl[idx] = __float2half_rn(rh - __half2float(h));
}

__global__ void gru_kernel(float* __restrict__ h_out)
{
    int idx = blockIdx.x * blockDim.x + threadIdx.x;
    if (idx >= BROWS * UDIM) return;
    int row = idx >> 9, col = idx & 511;
    const float* mx = g_mxi + (long long)row * THREEU;
    const float* mi = g_mxi + (long long)BROWS * THREEU + (long long)row * THREEU;
    float z  = 1.0f / (1.0f + __expf(-(mx[col] + mi[col])));
    float hp = g_hprev[idx];
    float hh = tanhf(mx[col + 1024] + g_mh[idx]);
    h_out[idx] = z * hp + (1.0f - z) * hh;
}

// ------------------------------ launch --------------------------------------
extern "C" void kernel_launch(void* const* d_in, const int* in_sizes, int n_in,
                              void* d_out, int out_size)
{
    const float* inputs    = (const float*)d_in[0];
    const float* h_tm1     = (const float*)d_in[1];
    const float* crohis_tm = (const float*)d_in[2];
    const float* W1   = (const float*)d_in[3];
    const float* W2   = (const float*)d_in[4];
    const float* w12  = (const float*)d_in[5];
    const float* u12  = (const float*)d_in[6];
    const float* v12  = (const float*)d_in[7];
    const float* w21  = (const float*)d_in[8];
    const float* u21  = (const float*)d_in[9];
    const float* v21  = (const float*)d_in[10];
    const float* croW = (const float*)d_in[11];
    const float* croB = (const float*)d_in[12];
    const float* decompW = (const float*)d_in[13];
    const float* decompB = (const float*)d_in[14];
    const float* kern  = (const float*)d_in[15];
    const float* rkern = (const float*)d_in[16];
    const float* bias  = (const float*)d_in[17];
    float* out = (float*)d_out;

    static bool attr_done = false;
    if (!attr_done) {
        cudaFuncSetAttribute(mma_gemm<0,true>,  cudaFuncAttributeMaxDynamicSharedMemorySize, SMEM_BYTES);
        cudaFuncSetAttribute(mma_gemm<0,false>, cudaFuncAttributeMaxDynamicSharedMemorySize, SMEM_BYTES);
        cudaFuncSetAttribute(mma_gemm<1,false>, cudaFuncAttributeMaxDynamicSharedMemorySize, SMEM_BYTES);
        cudaFuncSetAttribute(mma_gemm<2,true>,  cudaFuncAttributeMaxDynamicSharedMemorySize, SMEM_BYTES);
        cudaFuncSetAttribute(mma_gemm<3,false>, cudaFuncAttributeMaxDynamicSharedMemorySize, SMEM_BYTES);
        cudaFuncSetAttribute(mma_gemm<0,true>,  cudaFuncAttributePreferredSharedMemoryCarveout, 100);
        cudaFuncSetAttribute(mma_gemm<0,false>, cudaFuncAttributePreferredSharedMemoryCarveout, 100);
        cudaFuncSetAttribute(mma_gemm<1,false>, cudaFuncAttributePreferredSharedMemoryCarveout, 100);
        cudaFuncSetAttribute(mma_gemm<2,true>,  cudaFuncAttributePreferredSharedMemoryCarveout, 100);
        cudaFuncSetAttribute(mma_gemm<3,false>, cudaFuncAttributePreferredSharedMemoryCarveout, 100);
        attr_done = true;
    }

    __half *pBW,*pBP,*pBV,*pBD,*pBC,*pBK,*pBR,
           *pEh,*pEl,*pXHh,*pXHl,*pCRh,*pCRl,*pRHh,*pRHl;
    float *pEf,*pSf,*pVf,*pHP,*pMXI,*pMH,*pZB;
    cudaGetSymbolAddress((void**)&pBW,g_BW);
    cudaGetSymbolAddress((void**)&pBP,g_BP);
    cudaGetSymbolAddress((void**)&pBV,g_BV);
    cudaGetSymbolAddress((void**)&pBD,g_BD);
    cudaGetSymbolAddress((void**)&pBC,g_BC);
    cudaGetSymbolAddress((void**)&pBK,g_BK);
    cudaGetSymbolAddress((void**)&pBR,g_BR);
    cudaGetSymbolAddress((void**)&pEf,g_embf);
    cudaGetSymbolAddress((void**)&pEh,g_embh); cudaGetSymbolAddress((void**)&pEl,g_embl);
    cudaGetSymbolAddress((void**)&pSf,g_Sf);   cudaGetSymbolAddress((void**)&pVf,g_Vf);
    cudaGetSymbolAddress((void**)&pXHh,g_xhh); cudaGetSymbolAddress((void**)&pXHl,g_xhl);
    cudaGetSymbolAddress((void**)&pHP,g_hprev);
    cudaGetSymbolAddress((void**)&pCRh,g_croh); cudaGetSymbolAddress((void**)&pCRl,g_crol);
    cudaGetSymbolAddress((void**)&pMXI,g_mxi);
    cudaGetSymbolAddress((void**)&pRHh,g_rhh); cudaGetSymbolAddress((void**)&pRHl,g_rhl);
    cudaGetSymbolAddress((void**)&pMH,g_mh);   cudaGetSymbolAddress((void**)&pZB,g_zbias);

    // batched weight transpose+convert (one launch)
    TPack tp;
    TDesc* d = tp.d;
    d[0]  = {W1,      256, 2000, 256,  pBW,           2048, 0,   2048};
    d[1]  = {W2,      256, 2000, 256,  pBW+256*2048,  2048, 0,   2048};
    d[2]  = {w12,     256, 256,  256,  pBP,           512,  0,   256};
    d[3]  = {u12,     256, 256,  256,  pBP,           512,  256, 256};
    d[4]  = {u21,     256, 256,  256,  pBP+256*512,   512,  0,   256};
    d[5]  = {w21,     256, 256,  256,  pBP+256*512,   512,  256, 256};
    d[6]  = {v12,     256, 256,  256,  pBV,           256,  0,   256};
    d[7]  = {v21,     256, 256,  256,  pBV+256*256,   256,  0,   256};
    d[8]  = {decompW, 512, 512,  512,  pBD,           512,  0,   512};
    d[9]  = {croW,    512, 512,  512,  pBC,           512,  0,   512};
    d[10] = {kern,    1536, 512, 1536, pBK,           512,  0,   512};
    d[11] = {rkern,   1536, 512, 1536, pBK+1536*512,  512,  0,   512};
    d[12] = {rkern+1024, 1536, 512, 512, pBR,         512,  0,   512};
    tp.pre[0] = 0;
    for (int i = 0; i < 13; ++i)
        tp.pre[i+1] = tp.pre[i] + (d[i].N >> 5) * (d[i].Kw >> 5);
    tsplit_batch<<<tp.pre[13], dim3(32, 8)>>>(tp);

    // emb = inputs @ W  (fp32 A prefetched in-kernel; K padded to 2048)  grid 256
    mma_gemm<0,true><<<dim3(2,64,2), 256, SMEM_BYTES>>>(
        inputs, nullptr, 4000, 2000, 2000, pBW, (long long)256*2048,
        pEf, 512, 256, pEh, pEl, 2048, nullptr, nullptr, nullptr, 0, -1, 0);
    // S = emb @ [w;u]   (K=512)  grid 256
    mma_gemm<0,false><<<dim3(2,64,2), 256, SMEM_BYTES>>>(
        pEh, pEl, 512, 0, 512, pBP, (long long)256*512,
        pSf, 256, (long long)BROWS*256, nullptr, nullptr, 512,
        nullptr, nullptr, nullptr, 0, -1, 0);
    // V12 = emb2 @ v12, V21 = emb1 @ v21  (K=256)  grid 256
    mma_gemm<0,false><<<dim3(2,64,2), 256, SMEM_BYTES>>>(
        pEh+256, pEl+256, 512, -256, 256, pBV, (long long)256*256,
        pVf, 256, (long long)BROWS*256, nullptr, nullptr, 256,
        nullptr, nullptr, nullptr, 0, -1, 0);
    // attention + crohis_new (second half of d_out); warp per row-side
    attn_kernel<<<1024, 256>>>(crohis_tm, out + BU);
    // cro = tanh(crohis_tm @ decompW + decompB)  (fp32 A in-kernel)  grid 256
    mma_gemm<2,true><<<dim3(4,64,1), 256, SMEM_BYTES>>>(
        crohis_tm, nullptr, 512, 0, 512, pBD, 0,
        nullptr, 512, 0, pCRh, pCRl, 512, decompB, decompB, nullptr, 0, -1, 0);
    // h_prev = h_tm1 + tanh(cro @ croW + croB)  grid 256
    mma_gemm<3,false><<<dim3(4,64,1), 256, SMEM_BYTES>>>(
        pCRh, pCRl, 512, 0, 512, pBC, 0,
        pHP, 512, 0, pXHh + BU, pXHl + BU, 512, croB, croB, h_tm1, 512, -1, 0);
    // mx = x @ kernel + bias ; mi(first 1024 cols) = h_prev @ rkern  grid 1280
    mma_gemm<1,false><<<dim3(12,64,2), 256, SMEM_BYTES>>>(
        pXHh, pXHl, 512, BU, 512, pBK, (long long)1536*512,
        pMXI, 1536, (long long)BROWS*1536, nullptr, nullptr, 512,
        bias, pZB, nullptr, 0, 1, 8);
    // r gate, rh = r*h_prev (hi/lo)
    rgate_kernel<<<(BROWS*UDIM + 255)/256, 256>>>();
    // mh = rh @ rkern[:, 2U:]  grid 256
    mma_gemm<0,false><<<dim3(4,64,1), 256, SMEM_BYTES>>>(
        pRHh, pRHl, 512, 0, 512, pBR, 0,
        pMH, 512, 0, nullptr, nullptr, 512, nullptr, nullptr, nullptr, 0, -1, 0);
    // GRU combine -> h (first half of d_out)
    gru_kernel<<<(BROWS*UDIM + 255)/256, 256>>>(out);
}